// round 15
// baseline (speedup 1.0000x reference)
#include <cuda_runtime.h>

// SwinWindowAttention fused kernel: one CTA per window, fp32 f32x2 FMA.
// R9  (PASS 2067us): L1=64.4%; 7 warps re-read whole weight tile per GEMM.
// R13 (PASS 2038us): warp->(row,col) remap landed (fma 40.5->45.7) BUT the
//   R12 __ldg of rel_idx/bias was a mis-model: per-lane addresses span
//   ~25-32 cache lines per LDG (i*49 stride) -> ~9k extra L1 wf/CTA,
//   canceling the remap win (L1 64.4->77.4!).
// R14: revert to smem staging of bias_table + rel_idx (stride-49 LDS = 1 wf).
//   Remap intact, gathers back in smem.
// R15: resubmission of R14 verbatim (container-broker failure; not measured).

#define TOK 49
#define CD  128

namespace {
constexpr int THREADS = 256;
constexpr int XSTR = 132;                  // padded x row stride (floats)
constexpr int RSTR = 36;                   // padded qkv row stride (floats)
constexpr int HSTR = TOK * RSTR;           // per-head stride = 1764
constexpr int TSTR = 4 * HSTR;             // per-tensor stride = 7056
// smem layout (floats):
constexpr int OFF_X    = 0;                // x window [49][132] / attn output  (6468)
constexpr int OFF_QKV  = 6480;             // q,k,v each [4][HSTR]              (21168)
constexpr int OFF_WS   = 27648;            // weight tile transposed [128][132] (16896)
constexpr int OFF_BIAS = 44544;            // bias_table staged [169*4]         (676)
constexpr int OFF_RIDX = 45220;            // rel_idx staged [49*49]            (2401)
constexpr int SMEM_FLOATS = 47624;
constexpr int SMEM_BYTES  = SMEM_FLOATS * 4;   // 190496 B
constexpr float SCALE = 0.17677669529663687f;  // 32^-0.5
}

// ---- packed f32x2 helpers (sm_103a) ----------------------------------------
__device__ __forceinline__ unsigned long long pk2(float a, float b) {
    unsigned long long r;
    asm("mov.b64 %0, {%1, %2};" : "=l"(r)
        : "r"(__float_as_uint(a)), "r"(__float_as_uint(b)));
    return r;
}
__device__ __forceinline__ void fma2(unsigned long long& d,
                                     unsigned long long a, unsigned long long b) {
    asm("fma.rn.f32x2 %0, %1, %2, %3;" : "=l"(d) : "l"(a), "l"(b), "l"(d));
}
__device__ __forceinline__ void add2(unsigned long long& d, unsigned long long a) {
    asm("add.rn.f32x2 %0, %1, %2;" : "=l"(d) : "l"(a), "l"(d));
}
__device__ __forceinline__ float2 upk(unsigned long long v) {
    unsigned int lo, hi;
    asm("mov.b64 {%0, %1}, %2;" : "=r"(lo), "=r"(hi) : "l"(v));
    return make_float2(__uint_as_float(lo), __uint_as_float(hi));
}

// Stage a [128][128] row-major weight matrix into smem transposed:
// ws[k*132 + c] = w[c*128 + k]. Coalesced LDG.32, conflict-free STS.128.
__device__ __forceinline__ void stage_w(const float* __restrict__ wsrc, float* __restrict__ ws) {
    const int tid = threadIdx.x;
    #pragma unroll
    for (int it = 0; it < 16; ++it) {
        int idx = tid + it * THREADS;   // 0..4095
        int k  = idx & 127;             // lanes consecutive k -> coalesced
        int c0 = (idx >> 7) * 4;
        float a0 = wsrc[(c0 + 0) * 128 + k];
        float a1 = wsrc[(c0 + 1) * 128 + k];
        float a2 = wsrc[(c0 + 2) * 128 + k];
        float a3 = wsrc[(c0 + 3) * 128 + k];
        float4 v; v.x = a0; v.y = a1; v.z = a2; v.w = a3;
        *reinterpret_cast<float4*>(ws + k * 132 + c0) = v;
    }
}

// Same staging by one warp (lane t0 = 0..31), overlapped with attention.
__device__ __forceinline__ void stage_w_warp(const float* __restrict__ wsrc,
                                             float* __restrict__ ws, int t0) {
    #pragma unroll 4
    for (int it = 0; it < 128; ++it) {
        int idx = t0 + it * 32;
        int k  = idx & 127;
        int c0 = (idx >> 7) * 4;
        float a0 = wsrc[(c0 + 0) * 128 + k];
        float a1 = wsrc[(c0 + 1) * 128 + k];
        float a2 = wsrc[(c0 + 2) * 128 + k];
        float a3 = wsrc[(c0 + 3) * 128 + k];
        float4 v; v.x = a0; v.y = a1; v.z = a2; v.w = a3;
        *reinterpret_cast<float4*>(ws + k * 132 + c0) = v;
    }
}

// 7 rows x 4 cols register-tile GEMM over K=128 using f32x2 (col pairs).
__device__ __forceinline__ void gemm_7x4_f32x2(const float* __restrict__ xs,
                                               const float* __restrict__ ws,
                                               int r0, int c0,
                                               unsigned long long acc[7][2]) {
    #pragma unroll 4
    for (int k = 0; k < 128; k += 4) {
        unsigned long long wlo[4], whi[4];
        #pragma unroll
        for (int u = 0; u < 4; ++u) {
            ulonglong2 wv = *reinterpret_cast<const ulonglong2*>(ws + (k + u) * 132 + c0);
            wlo[u] = wv.x; whi[u] = wv.y;       // (c0,c0+1),(c0+2,c0+3)
        }
        #pragma unroll
        for (int r = 0; r < 7; ++r) {
            float4 xv = *reinterpret_cast<const float4*>(xs + (r0 + r) * XSTR + k);
            unsigned long long xx;
            xx = pk2(xv.x, xv.x); fma2(acc[r][0], xx, wlo[0]); fma2(acc[r][1], xx, whi[0]);
            xx = pk2(xv.y, xv.y); fma2(acc[r][0], xx, wlo[1]); fma2(acc[r][1], xx, whi[1]);
            xx = pk2(xv.z, xv.z); fma2(acc[r][0], xx, wlo[2]); fma2(acc[r][1], xx, whi[2]);
            xx = pk2(xv.w, xv.w); fma2(acc[r][0], xx, wlo[3]); fma2(acc[r][1], xx, whi[3]);
        }
    }
}

__global__ void __launch_bounds__(THREADS, 1)
swin_fused(const float* __restrict__ x,
           const float* __restrict__ qkv_w,
           const float* __restrict__ qkv_b,
           const float* __restrict__ out_w,
           const float* __restrict__ out_b,
           const float* __restrict__ bias_table,
           const int*   __restrict__ rel_idx,
           float* __restrict__ out)
{
    extern __shared__ float sm[];
    float* s_x    = sm + OFF_X;
    float* s_qkv  = sm + OFF_QKV;
    float* s_ws   = sm + OFF_WS;
    float* s_bias = sm + OFF_BIAS;
    int*   s_ridx = reinterpret_cast<int*>(sm + OFF_RIDX);

    const int tid = threadIdx.x;
    const float* xw = x + (size_t)blockIdx.x * (TOK * CD);

    // ---------------- Phase A: stage x (padded rows), bias table, rel_idx -----------
    for (int i = tid; i < TOK * 32; i += THREADS) {
        int row = i >> 5, c4 = (i & 31) * 4;
        *reinterpret_cast<float4*>(s_x + row * XSTR + c4) =
            *reinterpret_cast<const float4*>(xw + row * CD + c4);
    }
    for (int i = tid; i < 676; i += THREADS)
        s_bias[i] = bias_table[i];
    for (int i = tid; i < 2401; i += THREADS)
        s_ridx[i] = rel_idx[i];

    // GEMM role mapping: warp spans 4 col-groups x 8 row-groups.
    const int rg = tid & 7;             // row-group 0..7 (7 active)
    const int cg = tid >> 3;            // col-group 0..31
    const int r0 = rg * 7;
    const bool gact = (rg < 7);

    // ---------------- Phase B: QKV = x @ qkv_w^T + qkv_b  (3 passes of 128 cols) ----
    for (int p = 0; p < 3; ++p) {
        __syncthreads();                          // x ready / prior-pass readers done
        stage_w(qkv_w + p * 16384, s_ws);
        __syncthreads();
        if (gact) {
            const int c0 = cg * 4;
            unsigned long long acc[7][2];
            float4 bv = *reinterpret_cast<const float4*>(qkv_b + p * 128 + c0);
            #pragma unroll
            for (int r = 0; r < 7; ++r) {
                acc[r][0] = pk2(bv.x, bv.y);
                acc[r][1] = pk2(bv.z, bv.w);
            }
            gemm_7x4_f32x2(s_x, s_ws, r0, c0, acc);
            // scatter: s_qkv[p*TSTR + h*HSTR + row*RSTR + d]
            const int h  = cg >> 3;
            const int d0 = (cg & 7) * 4;
            float* dst = s_qkv + p * TSTR + h * HSTR + d0;
            #pragma unroll
            for (int r = 0; r < 7; ++r) {
                float2 a = upk(acc[r][0]), b = upk(acc[r][1]);
                float4 v; v.x = a.x; v.y = a.y; v.z = b.x; v.w = b.y;
                *reinterpret_cast<float4*>(dst + (r0 + r) * RSTR) = v;
            }
        }
    }
    __syncthreads();

    // ---------------- Phase C: attention (tids<196) || stage out_w (warp 7) ---------
    if (tid < 196) {
        const int h = tid / 49;
        const int i = tid - h * 49;
        const ulonglong2* qrow = reinterpret_cast<const ulonglong2*>(s_qkv + h * HSTR + i * RSTR);
        ulonglong2 qa[8];
        #pragma unroll
        for (int u = 0; u < 8; ++u) qa[u] = qrow[u];

        const float* kbase = s_qkv + TSTR     + h * HSTR;
        const float* vbase = s_qkv + 2 * TSTR + h * HSTR;
        const int*   ri    = s_ridx + i * 49;     // smem: lane stride 49 -> 1 wf

        float pr[49];
        float m = -1e30f;
        #pragma unroll
        for (int j = 0; j < 49; ++j) {
            const ulonglong2* kr = reinterpret_cast<const ulonglong2*>(kbase + j * RSTR);
            unsigned long long s0 = 0ull, s1 = 0ull, s2 = 0ull, s3 = 0ull;
            #pragma unroll
            for (int u = 0; u < 4; ++u) {        // 8 ulonglong2 = 32 dims
                ulonglong2 k0 = kr[2 * u], k1 = kr[2 * u + 1];
                fma2(s0, qa[2 * u].x,     k0.x);
                fma2(s1, qa[2 * u].y,     k0.y);
                fma2(s2, qa[2 * u + 1].x, k1.x);
                fma2(s3, qa[2 * u + 1].y, k1.y);
            }
            add2(s0, s1); add2(s2, s3); add2(s0, s2);
            float2 sp = upk(s0);
            float s = sp.x + sp.y;
            s = fmaf(s, SCALE, s_bias[ri[j] * 4 + h]);
            pr[j] = s;
            m = fmaxf(m, s);
        }
        float sum = 0.f;
        #pragma unroll
        for (int j = 0; j < 49; ++j) {
            float e = __expf(pr[j] - m);
            pr[j] = e;
            sum += e;
        }
        const float inv = 1.f / sum;

        unsigned long long o2[16];
        #pragma unroll
        for (int u = 0; u < 16; ++u) o2[u] = 0ull;
        #pragma unroll
        for (int j = 0; j < 49; ++j) {
            const unsigned long long pp = pk2(pr[j], pr[j]);
            const ulonglong2* vr = reinterpret_cast<const ulonglong2*>(vbase + j * RSTR);
            #pragma unroll
            for (int u = 0; u < 8; ++u) {
                ulonglong2 vv = vr[u];
                fma2(o2[2 * u + 0], pp, vv.x);
                fma2(o2[2 * u + 1], pp, vv.y);
            }
        }
        // write concat-head layout into s_x (padded rows): o_row[i][h*32+d]
        float* od = s_x + i * XSTR + h * 32;
        #pragma unroll
        for (int u = 0; u < 16; ++u) {
            float2 v = upk(o2[u]);
            od[2 * u + 0] = v.x * inv;
            od[2 * u + 1] = v.y * inv;
        }
    } else if (tid >= 224) {
        // Warp 7 (idle in attention) stages out_w concurrently; s_ws unused
        // since the post-Phase-B barrier.
        stage_w_warp(out_w, s_ws, tid - 224);
    }
    __syncthreads();

    // ---------------- Phase D: out = o @ out_w^T + out_b -----------------------------
    if (gact) {
        const int c0 = cg * 4;
        unsigned long long acc[7][2];
        float4 bv = *reinterpret_cast<const float4*>(out_b + c0);
        #pragma unroll
        for (int r = 0; r < 7; ++r) {
            acc[r][0] = pk2(bv.x, bv.y);
            acc[r][1] = pk2(bv.z, bv.w);
        }
        gemm_7x4_f32x2(s_x, s_ws, r0, c0, acc);
        float* dst = out + (size_t)blockIdx.x * (TOK * CD);
        #pragma unroll
        for (int r = 0; r < 7; ++r) {
            float2 a = upk(acc[r][0]), b = upk(acc[r][1]);
            float4 v; v.x = a.x; v.y = a.y; v.z = b.x; v.w = b.y;
            *reinterpret_cast<float4*>(dst + (r0 + r) * CD + c0) = v;
        }
    }
}

extern "C" void kernel_launch(void* const* d_in, const int* in_sizes, int n_in,
                              void* d_out, int out_size) {
    const float* x          = (const float*)d_in[0];
    const float* qkv_w      = (const float*)d_in[1];
    const float* qkv_b      = (const float*)d_in[2];
    const float* out_w      = (const float*)d_in[3];
    const float* out_b      = (const float*)d_in[4];
    const float* bias_table = (const float*)d_in[5];
    const int*   rel_idx    = (const int*)d_in[6];
    float* out = (float*)d_out;

    const int nwin = in_sizes[0] / (TOK * CD);   // 8192

    cudaFuncSetAttribute(swin_fused, cudaFuncAttributeMaxDynamicSharedMemorySize, SMEM_BYTES);
    swin_fused<<<nwin, THREADS, SMEM_BYTES>>>(x, qkv_w, qkv_b, out_w, out_b,
                                              bias_table, rel_idx, out);
}

// round 17
// speedup vs baseline: 1.0415x; 1.0415x over previous
#include <cuda_runtime.h>

// SwinWindowAttention fused kernel: one CTA per window, fp32 f32x2 FMA.
// Measured: R9 2067us (old map) / R13 2038 (remap+__ldg) / R15 2102 (remap+smem)
//   -> remap RAISED L1 (64.4->73.9): it broke the x-row warp-broadcast.
//   All scalar variants latency-bound: occ 12.4% (2 warps/SMSP), issue 33%.
// R16: 512-thread CTA (16 warps = 4/SMSP, occ ~25%) with the R9 mapping
//   column-halved: warp pair shares a row-group (x stays broadcast), splits
//   cols 64/64; lane = 7 rows x 2 cols (acc: 7 ulonglong). Weight LDS.64 =
//   2 wf/warp/load, total w-traffic unchanged vs R9. Per-element FMA order
//   identical -> same rel_err. Phase C unchanged; warp 15 stages out_w.
// R17: resubmission of R16 verbatim (container-broker failure; not measured).

#define TOK 49
#define CD  128

namespace {
constexpr int THREADS = 512;
constexpr int XSTR = 132;                  // padded x row stride (floats)
constexpr int RSTR = 36;                   // padded qkv row stride (floats)
constexpr int HSTR = TOK * RSTR;           // per-head stride = 1764
constexpr int TSTR = 4 * HSTR;             // per-tensor stride = 7056
// smem layout (floats):
constexpr int OFF_X    = 0;                // x window [49][132] / attn output  (6468)
constexpr int OFF_QKV  = 6480;             // q,k,v each [4][HSTR]              (21168)
constexpr int OFF_WS   = 27648;            // weight tile transposed [128][132] (16896)
constexpr int OFF_BIAS = 44544;            // bias_table staged [169*4]         (676)
constexpr int OFF_RIDX = 45220;            // rel_idx staged [49*49]            (2401)
constexpr int SMEM_FLOATS = 47624;
constexpr int SMEM_BYTES  = SMEM_FLOATS * 4;   // 190496 B
constexpr float SCALE = 0.17677669529663687f;  // 32^-0.5
}

// ---- packed f32x2 helpers (sm_103a) ----------------------------------------
__device__ __forceinline__ unsigned long long pk2(float a, float b) {
    unsigned long long r;
    asm("mov.b64 %0, {%1, %2};" : "=l"(r)
        : "r"(__float_as_uint(a)), "r"(__float_as_uint(b)));
    return r;
}
__device__ __forceinline__ void fma2(unsigned long long& d,
                                     unsigned long long a, unsigned long long b) {
    asm("fma.rn.f32x2 %0, %1, %2, %3;" : "=l"(d) : "l"(a), "l"(b), "l"(d));
}
__device__ __forceinline__ void add2(unsigned long long& d, unsigned long long a) {
    asm("add.rn.f32x2 %0, %1, %2;" : "=l"(d) : "l"(a), "l"(d));
}
__device__ __forceinline__ float2 upk(unsigned long long v) {
    unsigned int lo, hi;
    asm("mov.b64 {%0, %1}, %2;" : "=r"(lo), "=r"(hi) : "l"(v));
    return make_float2(__uint_as_float(lo), __uint_as_float(hi));
}

// Stage a [128][128] row-major weight matrix into smem transposed:
// ws[k*132 + c] = w[c*128 + k]. Coalesced LDG.32, conflict-free STS.128.
__device__ __forceinline__ void stage_w(const float* __restrict__ wsrc, float* __restrict__ ws) {
    const int tid = threadIdx.x;
    #pragma unroll
    for (int it = 0; it < (128 * 32) / THREADS; ++it) {
        int idx = tid + it * THREADS;   // 0..4095
        int k  = idx & 127;             // lanes consecutive k -> coalesced
        int c0 = (idx >> 7) * 4;
        float a0 = wsrc[(c0 + 0) * 128 + k];
        float a1 = wsrc[(c0 + 1) * 128 + k];
        float a2 = wsrc[(c0 + 2) * 128 + k];
        float a3 = wsrc[(c0 + 3) * 128 + k];
        float4 v; v.x = a0; v.y = a1; v.z = a2; v.w = a3;
        *reinterpret_cast<float4*>(ws + k * 132 + c0) = v;
    }
}

// Same staging by one warp (lane t0 = 0..31), overlapped with attention.
__device__ __forceinline__ void stage_w_warp(const float* __restrict__ wsrc,
                                             float* __restrict__ ws, int t0) {
    #pragma unroll 4
    for (int it = 0; it < 128; ++it) {
        int idx = t0 + it * 32;
        int k  = idx & 127;
        int c0 = (idx >> 7) * 4;
        float a0 = wsrc[(c0 + 0) * 128 + k];
        float a1 = wsrc[(c0 + 1) * 128 + k];
        float a2 = wsrc[(c0 + 2) * 128 + k];
        float a3 = wsrc[(c0 + 3) * 128 + k];
        float4 v; v.x = a0; v.y = a1; v.z = a2; v.w = a3;
        *reinterpret_cast<float4*>(ws + k * 132 + c0) = v;
    }
}

// 7 rows x 2 cols register-tile GEMM over K=128 using f32x2 (one col pair).
// x rows broadcast per warp (rg shared); w read as LDS.64 (2 wf/warp).
__device__ __forceinline__ void gemm_7x2_f32x2(const float* __restrict__ xs,
                                               const float* __restrict__ ws,
                                               int r0, int c0,
                                               unsigned long long acc[7]) {
    #pragma unroll 4
    for (int k = 0; k < 128; k += 4) {
        unsigned long long wv[4];
        #pragma unroll
        for (int u = 0; u < 4; ++u)
            wv[u] = *reinterpret_cast<const unsigned long long*>(ws + (k + u) * 132 + c0);
        #pragma unroll
        for (int r = 0; r < 7; ++r) {
            float4 xv = *reinterpret_cast<const float4*>(xs + (r0 + r) * XSTR + k);
            fma2(acc[r], pk2(xv.x, xv.x), wv[0]);
            fma2(acc[r], pk2(xv.y, xv.y), wv[1]);
            fma2(acc[r], pk2(xv.z, xv.z), wv[2]);
            fma2(acc[r], pk2(xv.w, xv.w), wv[3]);
        }
    }
}

__global__ void __launch_bounds__(THREADS, 1)
swin_fused(const float* __restrict__ x,
           const float* __restrict__ qkv_w,
           const float* __restrict__ qkv_b,
           const float* __restrict__ out_w,
           const float* __restrict__ out_b,
           const float* __restrict__ bias_table,
           const int*   __restrict__ rel_idx,
           float* __restrict__ out)
{
    extern __shared__ float sm[];
    float* s_x    = sm + OFF_X;
    float* s_qkv  = sm + OFF_QKV;
    float* s_ws   = sm + OFF_WS;
    float* s_bias = sm + OFF_BIAS;
    int*   s_ridx = reinterpret_cast<int*>(sm + OFF_RIDX);

    const int tid = threadIdx.x;
    const float* xw = x + (size_t)blockIdx.x * (TOK * CD);

    // ---------------- Phase A: stage x (padded rows), bias table, rel_idx -----------
    for (int i = tid; i < TOK * 32; i += THREADS) {
        int row = i >> 5, c4 = (i & 31) * 4;
        *reinterpret_cast<float4*>(s_x + row * XSTR + c4) =
            *reinterpret_cast<const float4*>(xw + row * CD + c4);
    }
    for (int i = tid; i < 676; i += THREADS)
        s_bias[i] = bias_table[i];
    for (int i = tid; i < 2401; i += THREADS)
        s_ridx[i] = rel_idx[i];

    // GEMM role mapping: warp pair shares row-group (x broadcast), splits cols.
    const int warp  = tid >> 5;         // 0..15 (14 active for GEMM)
    const int lane  = tid & 31;
    const int rg    = warp >> 1;        // 0..6 (for warp<14)
    const int chalf = warp & 1;
    const int r0    = rg * 7;
    const int c0    = chalf * 64 + lane * 2;   // even -> 8B-aligned pairs
    const bool gact = (warp < 14);

    // ---------------- Phase B: QKV = x @ qkv_w^T + qkv_b  (3 passes of 128 cols) ----
    for (int p = 0; p < 3; ++p) {
        __syncthreads();                          // x ready / prior-pass readers done
        stage_w(qkv_w + p * 16384, s_ws);
        __syncthreads();
        if (gact) {
            unsigned long long acc[7];
            float2 bv = *reinterpret_cast<const float2*>(qkv_b + p * 128 + c0);
            const unsigned long long binit = pk2(bv.x, bv.y);
            #pragma unroll
            for (int r = 0; r < 7; ++r) acc[r] = binit;
            gemm_7x2_f32x2(s_x, s_ws, r0, c0, acc);
            // scatter: s_qkv[p*TSTR + h*HSTR + row*RSTR + d], pair (c0,c0+1)
            const int h = c0 >> 5;
            const int d = c0 & 31;
            float* dst = s_qkv + p * TSTR + h * HSTR + d;
            #pragma unroll
            for (int r = 0; r < 7; ++r)
                *reinterpret_cast<unsigned long long*>(dst + (r0 + r) * RSTR) = acc[r];
        }
    }
    __syncthreads();

    // ---------------- Phase C: attention (tids<196) || stage out_w (warp 15) --------
    if (tid < 196) {
        const int h = tid / 49;
        const int i = tid - h * 49;
        const ulonglong2* qrow = reinterpret_cast<const ulonglong2*>(s_qkv + h * HSTR + i * RSTR);
        ulonglong2 qa[8];
        #pragma unroll
        for (int u = 0; u < 8; ++u) qa[u] = qrow[u];

        const float* kbase = s_qkv + TSTR     + h * HSTR;
        const float* vbase = s_qkv + 2 * TSTR + h * HSTR;
        const int*   ri    = s_ridx + i * 49;     // smem: lane stride 49 -> 1 wf

        float pr[49];
        float m = -1e30f;
        #pragma unroll
        for (int j = 0; j < 49; ++j) {
            const ulonglong2* kr = reinterpret_cast<const ulonglong2*>(kbase + j * RSTR);
            unsigned long long s0 = 0ull, s1 = 0ull, s2 = 0ull, s3 = 0ull;
            #pragma unroll
            for (int u = 0; u < 4; ++u) {        // 8 ulonglong2 = 32 dims
                ulonglong2 k0 = kr[2 * u], k1 = kr[2 * u + 1];
                fma2(s0, qa[2 * u].x,     k0.x);
                fma2(s1, qa[2 * u].y,     k0.y);
                fma2(s2, qa[2 * u + 1].x, k1.x);
                fma2(s3, qa[2 * u + 1].y, k1.y);
            }
            add2(s0, s1); add2(s2, s3); add2(s0, s2);
            float2 sp = upk(s0);
            float s = sp.x + sp.y;
            s = fmaf(s, SCALE, s_bias[ri[j] * 4 + h]);
            pr[j] = s;
            m = fmaxf(m, s);
        }
        float sum = 0.f;
        #pragma unroll
        for (int j = 0; j < 49; ++j) {
            float e = __expf(pr[j] - m);
            pr[j] = e;
            sum += e;
        }
        const float inv = 1.f / sum;

        unsigned long long o2[16];
        #pragma unroll
        for (int u = 0; u < 16; ++u) o2[u] = 0ull;
        #pragma unroll
        for (int j = 0; j < 49; ++j) {
            const unsigned long long pp = pk2(pr[j], pr[j]);
            const ulonglong2* vr = reinterpret_cast<const ulonglong2*>(vbase + j * RSTR);
            #pragma unroll
            for (int u = 0; u < 8; ++u) {
                ulonglong2 vv = vr[u];
                fma2(o2[2 * u + 0], pp, vv.x);
                fma2(o2[2 * u + 1], pp, vv.y);
            }
        }
        // write concat-head layout into s_x (padded rows): o_row[i][h*32+d]
        float* od = s_x + i * XSTR + h * 32;
        #pragma unroll
        for (int u = 0; u < 16; ++u) {
            float2 v = upk(o2[u]);
            od[2 * u + 0] = v.x * inv;
            od[2 * u + 1] = v.y * inv;
        }
    } else if (tid >= 480) {
        // Warp 15 (idle in attention) stages out_w; s_ws unused since the
        // post-Phase-B barrier.
        stage_w_warp(out_w, s_ws, tid - 480);
    }
    __syncthreads();

    // ---------------- Phase D: out = o @ out_w^T + out_b -----------------------------
    if (gact) {
        unsigned long long acc[7];
        float2 bv = *reinterpret_cast<const float2*>(out_b + c0);
        const unsigned long long binit = pk2(bv.x, bv.y);
        #pragma unroll
        for (int r = 0; r < 7; ++r) acc[r] = binit;
        gemm_7x2_f32x2(s_x, s_ws, r0, c0, acc);
        float* dst = out + (size_t)blockIdx.x * (TOK * CD);
        #pragma unroll
        for (int r = 0; r < 7; ++r)
            *reinterpret_cast<unsigned long long*>(dst + (r0 + r) * CD + c0) = acc[r];
    }
}

extern "C" void kernel_launch(void* const* d_in, const int* in_sizes, int n_in,
                              void* d_out, int out_size) {
    const float* x          = (const float*)d_in[0];
    const float* qkv_w      = (const float*)d_in[1];
    const float* qkv_b      = (const float*)d_in[2];
    const float* out_w      = (const float*)d_in[3];
    const float* out_b      = (const float*)d_in[4];
    const float* bias_table = (const float*)d_in[5];
    const int*   rel_idx    = (const int*)d_in[6];
    float* out = (float*)d_out;

    const int nwin = in_sizes[0] / (TOK * CD);   // 8192

    cudaFuncSetAttribute(swin_fused, cudaFuncAttributeMaxDynamicSharedMemorySize, SMEM_BYTES);
    swin_fused<<<nwin, THREADS, SMEM_BYTES>>>(x, qkv_w, qkv_b, out_w, out_b,
                                              bias_table, rel_idx, out);
}